// round 7
// baseline (speedup 1.0000x reference)
#include <cuda_runtime.h>
#include <cuda_bf16.h>

// Problem: GraphSequenceOrderer_53257594470659
// B=32, K=1024, D=256. Output (f32, concatenated):
//   [0, B*K*D)           ordered_slots
//   [B*K*D, B*K*D+B*K)   order (as float)
//   [.. + B*K)           reverse_order (as float)

#define B 32
#define K 1024
#define D 256
#define NBUCKET 256           // 16x16 grid -> hilbert index in [0,256)
#define NWARP 32              // 1024 threads / 32
#define SCATTER_BLOCKS 1024   // 32 rows per block
#define BLOCKS_PER_BATCH 32   // scatter blocks per batch

// inverse permutation (position within batch) for the scatter phase
__device__ int g_rev[B * K];
// per-batch ready flag + completion counter (both return to 0 every run)
__device__ unsigned g_flag[B];
__device__ unsigned g_done[B];

__device__ __forceinline__ int hilbert_index(int x, int y) {
    int d = 0;
#pragma unroll
    for (int s = 8; s > 0; s >>= 1) {
        int rx = (x & s) ? 1 : 0;
        int ry = (y & s) ? 1 : 0;
        d += s * s * ((3 * rx) ^ ry);
        if (ry == 0) {
            if (rx == 1) {
                int t = x;
                x = s - 1 - y;
                y = s - 1 - t;
            } else {
                int t = x; x = y; y = t;
            }
        }
    }
    return d;
}

__device__ __forceinline__ unsigned ld_acquire(const unsigned* p) {
    unsigned v;
    asm volatile("ld.acquire.gpu.u32 %0, [%1];" : "=r"(v) : "l"(p) : "memory");
    return v;
}
__device__ __forceinline__ void st_release(unsigned* p, unsigned v) {
    asm volatile("st.release.gpu.u32 [%0], %1;" :: "l"(p), "r"(v) : "memory");
}

// Fused kernel. Blocks 0..31: stable counting sort for batch b = blockIdx.x.
// Blocks 32..: scatter 32 rows each (one warp per row), overlapping their
// sequential slot reads with the sort via a per-batch flag spin.
__global__ __launch_bounds__(1024, 1)
void fused_kernel(const float* __restrict__ centroids,
                  const float4* __restrict__ slots,
                  float* __restrict__ out) {
    __shared__ int hist[NBUCKET * NWARP];  // 32 KB (also reserved by scatter blocks)
    __shared__ int warp_sums[NWARP];

    const int tid  = threadIdx.x;
    const int lane = tid & 31;
    const int warp = tid >> 5;

    if (blockIdx.x < B) {
        // ================= SORT (one CTA per batch) =================
        const int b = blockIdx.x;
        const int i = tid;

        float* out_order_f = out + (size_t)B * K * D;
        float* out_rev_f   = out_order_f + (size_t)B * K;

        // --- hilbert key ---
        const float2 c = ((const float2*)centroids)[b * K + i];
        float cxf = fminf(fmaxf(c.x * 15.0f, 0.0f), 15.0f);
        float cyf = fminf(fmaxf(c.y * 15.0f, 0.0f), 15.0f);
        int h = hilbert_index((int)cxf, (int)cyf);

        // --- zero histogram ---
#pragma unroll
        for (int j = 0; j < (NBUCKET * NWARP) / 1024; j++)
            hist[i + j * 1024] = 0;
        __syncthreads();

        // --- per-warp counts + stable intra-warp rank via match ---
        unsigned mask = __match_any_sync(0xffffffffu, h);
        int rank = __popc(mask & ((1u << lane) - 1u));
        int leader = __ffs(mask) - 1;
        if (lane == leader)
            hist[h * NWARP + warp] = __popc(mask);
        __syncthreads();

        // --- exclusive scan of 8192 entries (bucket-major => stable) ---
        int base = i * 8;
        int local[8];
        int lsum = 0;
#pragma unroll
        for (int j = 0; j < 8; j++) { local[j] = hist[base + j]; lsum += local[j]; }

        int v = lsum;
#pragma unroll
        for (int o = 1; o < 32; o <<= 1) {
            int n = __shfl_up_sync(0xffffffffu, v, o);
            if (lane >= o) v += n;
        }
        if (lane == 31) warp_sums[warp] = v;
        __syncthreads();
        if (warp == 0) {
            int w = warp_sums[lane];
            int incl = w;
#pragma unroll
            for (int o = 1; o < 32; o <<= 1) {
                int n = __shfl_up_sync(0xffffffffu, incl, o);
                if (lane >= o) incl += n;
            }
            warp_sums[lane] = incl - w;
        }
        __syncthreads();
        int excl = (v - lsum) + warp_sums[warp];

        int run = excl;
#pragma unroll
        for (int j = 0; j < 8; j++) {
            hist[base + j] = run;
            run += local[j];
        }
        __syncthreads();

        // --- emit ---
        int pos = hist[h * NWARP + warp] + rank;
        g_rev[b * K + i] = pos;
        out_order_f[b * K + pos] = (float)i;
        out_rev_f[b * K + i]   = (float)pos;

        // publish: all g_rev writes of this CTA visible before flag
        __syncthreads();
        if (tid == 0)
            st_release(&g_flag[b], 1u);
    } else {
        // ================= SCATTER (32 rows per CTA, 1 warp/row) =========
        const int sblk = blockIdx.x - B;
        const int row  = sblk * 32 + warp;       // [0, B*K)
        const int b    = row >> 10;
        const int bofs = b << 10;

        // sequential slot reads issue immediately (independent of the sort)
        const float4* s = slots + ((size_t)row << 6);
        const float4 v0 = s[lane];
        const float4 v1 = s[lane + 32];

        // wait until this batch's permutation is published
        if (tid == 0) {
            while (ld_acquire(&g_flag[b]) == 0) { }
        }
        __syncthreads();

        const int dst = g_rev[row];              // warp-broadcast
        float4* o = (float4*)out + ((size_t)(bofs + dst) << 6);
        o[lane]      = v0;
        o[lane + 32] = v1;

        // reset flags for the next graph replay: last block of each batch
        __syncthreads();
        if (tid == 0) {
            unsigned old = atomicAdd(&g_done[b], 1u);
            if (old == BLOCKS_PER_BATCH - 1) {
                g_done[b] = 0u;
                __threadfence();
                g_flag[b] = 0u;
            }
        }
    }
}

extern "C" void kernel_launch(void* const* d_in, const int* in_sizes, int n_in,
                              void* d_out, int out_size) {
    const float* slots     = (const float*)d_in[0];
    // d_in[1] = adj: unused by the reference
    const float* centroids = (const float*)d_in[2];

    fused_kernel<<<B + SCATTER_BLOCKS, 1024>>>(centroids,
                                               (const float4*)slots,
                                               (float*)d_out);
}

// round 8
// speedup vs baseline: 1.3624x; 1.3624x over previous
#include <cuda_runtime.h>
#include <cuda_bf16.h>

// Problem: GraphSequenceOrderer_53257594470659
// B=32, K=1024, D=256. Output (f32, concatenated):
//   [0, B*K*D)           ordered_slots
//   [B*K*D, B*K*D+B*K)   order (as float)
//   [.. + B*K)           reverse_order (as float)

#define B 32
#define K 1024
#define D 256
#define NBUCKET 256   // 16x16 grid -> hilbert index in [0,256)
#define NWARP 32      // 1024 threads / 32

// inverse permutation (position within batch) for the scatter kernel
__device__ int g_rev[B * K];

__device__ __forceinline__ int hilbert_index(int x, int y) {
    int d = 0;
#pragma unroll
    for (int s = 8; s > 0; s >>= 1) {
        int rx = (x & s) ? 1 : 0;
        int ry = (y & s) ? 1 : 0;
        d += s * s * ((3 * rx) ^ ry);
        if (ry == 0) {
            if (rx == 1) {
                int t = x;
                x = s - 1 - y;
                y = s - 1 - t;
            } else {
                int t = x; x = y; y = t;
            }
        }
    }
    return d;
}

// One CTA per batch. 1024 threads, one key each.
// Stable counting sort over 256 hilbert buckets.
__global__ __launch_bounds__(1024, 1)
void sort_kernel(const float* __restrict__ centroids,
                 float* __restrict__ out_order_f,
                 float* __restrict__ out_rev_f) {
    const int b = blockIdx.x;
    const int i = threadIdx.x;
    const int lane = i & 31;
    const int warp = i >> 5;

    __shared__ int hist[NBUCKET * NWARP];  // 32 KB, bucket-major [bucket][warp]
    __shared__ int warp_sums[NWARP];

    // --- hilbert key ---
    const float2 c = ((const float2*)centroids)[b * K + i];
    float cxf = fminf(fmaxf(c.x * 15.0f, 0.0f), 15.0f);
    float cyf = fminf(fmaxf(c.y * 15.0f, 0.0f), 15.0f);
    int h = hilbert_index((int)cxf, (int)cyf);

    // --- zero histogram ---
#pragma unroll
    for (int j = 0; j < (NBUCKET * NWARP) / 1024; j++)
        hist[i + j * 1024] = 0;
    __syncthreads();

    // --- per-warp counts + stable intra-warp rank via match ---
    unsigned mask = __match_any_sync(0xffffffffu, h);
    int rank = __popc(mask & ((1u << lane) - 1u));   // # earlier lanes, same bucket
    int leader = __ffs(mask) - 1;
    if (lane == leader)
        hist[h * NWARP + warp] = __popc(mask);
    __syncthreads();

    // --- exclusive scan of 8192 entries (bucket-major => stable order) ---
    int base = i * 8;
    int local[8];
    int lsum = 0;
#pragma unroll
    for (int j = 0; j < 8; j++) { local[j] = hist[base + j]; lsum += local[j]; }

    int v = lsum;
#pragma unroll
    for (int o = 1; o < 32; o <<= 1) {
        int n = __shfl_up_sync(0xffffffffu, v, o);
        if (lane >= o) v += n;
    }
    if (lane == 31) warp_sums[warp] = v;
    __syncthreads();
    if (warp == 0) {
        int w = warp_sums[lane];
        int incl = w;
#pragma unroll
        for (int o = 1; o < 32; o <<= 1) {
            int n = __shfl_up_sync(0xffffffffu, incl, o);
            if (lane >= o) incl += n;
        }
        warp_sums[lane] = incl - w;  // exclusive
    }
    __syncthreads();
    int excl = (v - lsum) + warp_sums[warp];

    int run = excl;
#pragma unroll
    for (int j = 0; j < 8; j++) {
        hist[base + j] = run;
        run += local[j];
    }
    __syncthreads();

    // --- emit permutation first, then release the dependent scatter grid ---
    int pos = hist[h * NWARP + warp] + rank;     // stable output position
    g_rev[b * K + i] = pos;                      // inverse permutation

    __threadfence();        // g_rev visible device-wide before trigger
    __syncthreads();        // whole CTA done writing g_rev
    cudaTriggerProgrammaticLaunchCompletion();

    // f32 output tail (not needed by the scatter) after the trigger
    out_order_f[b * K + pos] = (float)i;
    out_rev_f[b * K + i]   = (float)pos;
}

// Permutation SCATTER with PDL: out[rev[i]] = slots[i].
// Front-issues its sequential slot reads (independent of the sort), then
// waits on the primary grid, then resolves destinations and stores.
// One warp per row; 8 warps/block; grid = B*K/8 = 4096 blocks.
__global__ __launch_bounds__(256)
void scatter_kernel(const float4* __restrict__ slots, float4* __restrict__ out) {
    const int row  = blockIdx.x * 8 + (threadIdx.x >> 5);  // [0, B*K)
    const int lane = threadIdx.x & 31;
    const int bofs = (row >> 10) << 10;                    // batch base row (b*K)

    // sequential reads issue immediately, overlapping the sort's tail
    const float4* s = slots + ((size_t)row << 6);
    const float4 v0 = s[lane];
    const float4 v1 = s[lane + 32];

    // wait for the sort grid's g_rev to be visible
    cudaGridDependencySynchronize();

    const int dst = g_rev[row];                            // warp-broadcast
    float4* o = out + ((size_t)(bofs + dst) << 6);
    o[lane]      = v0;
    o[lane + 32] = v1;
}

extern "C" void kernel_launch(void* const* d_in, const int* in_sizes, int n_in,
                              void* d_out, int out_size) {
    const float* slots     = (const float*)d_in[0];
    // d_in[1] = adj: unused by the reference
    const float* centroids = (const float*)d_in[2];

    float* out = (float*)d_out;
    float* out_order = out + (size_t)B * K * D;
    float* out_rev   = out_order + (size_t)B * K;

    sort_kernel<<<B, 1024>>>(centroids, out_order, out_rev);

    // scatter with programmatic dependent launch on the sort
    cudaLaunchConfig_t cfg = {};
    cfg.gridDim  = dim3((B * K) / 8, 1, 1);
    cfg.blockDim = dim3(256, 1, 1);
    cfg.dynamicSmemBytes = 0;
    cfg.stream = 0;  // legacy default stream == capture stream

    cudaLaunchAttribute attrs[1];
    attrs[0].id = cudaLaunchAttributeProgrammaticStreamSerialization;
    attrs[0].val.programmaticStreamSerializationAllowed = 1;
    cfg.attrs = attrs;
    cfg.numAttrs = 1;

    cudaLaunchKernelEx(&cfg, scatter_kernel, (const float4*)slots, (float4*)out);
}